// round 1
// baseline (speedup 1.0000x reference)
#include <cuda_runtime.h>
#include <cuda_bf16.h>

#define IN_F   4096
#define OUT_F  4096
#define NTOK   16384
#define BW     8
#define KW     17          // 2*BW+1
#define NO     4           // outputs per thread
#define WARPS  8           // warps per block
#define GY     512         // token groups (grid.y)

// warp covers 32*NO = 128 consecutive outputs; block covers 1024; grid.x = 4.
__global__ __launch_bounds__(256) void band_linear_kernel(
    const float* __restrict__ x,
    const float* __restrict__ w,
    const float* __restrict__ bias,
    float* __restrict__ out)
{
    const int warp = threadIdx.x >> 5;
    const int lane = threadIdx.x & 31;
    const int o_base = (blockIdx.x * WARPS + warp) * (32 * NO) + lane * NO;

    // ---- load 4x17 band weights + bias into registers (once per block) ----
    float wr[NO][KW];
    float br[NO];
#pragma unroll
    for (int oo = 0; oo < NO; ++oo) {
        const int o = o_base + oo;
        br[oo] = bias[o];
#pragma unroll
        for (int k = 0; k < KW; ++k) {
            const int i = o - BW + k;
            wr[oo][k] = (i >= 0 && i < IN_F) ? w[(long)o * IN_F + i] : 0.0f;
        }
    }

    const int xs = o_base - BW;   // window start; multiple of 4 shifted by -8 -> still mult of 4

    for (int n = blockIdx.y; n < NTOK; n += GY) {
        const float* __restrict__ xrow = x + (long)n * IN_F;

        // ---- sliding x window: 20 floats = 5 aligned float4 chunks ----
        float xr[NO + 2 * BW];     // 20
#pragma unroll
        for (int c = 0; c < 5; ++c) {
            int s = xs + 4 * c;
            // chunks are never partially OOB (xs % 4 == 0); clamped chunks pair
            // only with zero weights, so their (finite) values are harmless.
            s = s < 0 ? 0 : (s > IN_F - 4 ? IN_F - 4 : s);
            const float4 v = *reinterpret_cast<const float4*>(xrow + s);
            xr[4 * c + 0] = v.x;
            xr[4 * c + 1] = v.y;
            xr[4 * c + 2] = v.z;
            xr[4 * c + 3] = v.w;
        }

        // ---- 4 outputs, 17 taps each ----
        float acc[NO];
#pragma unroll
        for (int oo = 0; oo < NO; ++oo) {
            float a = br[oo];
#pragma unroll
            for (int k = 0; k < KW; ++k)
                a = fmaf(wr[oo][k], xr[oo + k], a);
            acc[oo] = a;
        }

        float4 o4;
        o4.x = acc[0]; o4.y = acc[1]; o4.z = acc[2]; o4.w = acc[3];
        *reinterpret_cast<float4*>(out + (long)n * OUT_F + o_base) = o4;
    }
}

extern "C" void kernel_launch(void* const* d_in, const int* in_sizes, int n_in,
                              void* d_out, int out_size)
{
    const float* x    = (const float*)d_in[0];   // [NTOK, IN_F]
    const float* w    = (const float*)d_in[1];   // [OUT_F, IN_F]
    const float* bias = (const float*)d_in[2];   // [OUT_F]
    // d_in[3] = mask, implied by the band structure; unused.
    float* out = (float*)d_out;

    dim3 grid(OUT_F / (WARPS * 32 * NO), GY);    // (4, 512)
    dim3 block(WARPS * 32);                      // 256
    band_linear_kernel<<<grid, block>>>(x, w, bias, out);
}